// round 14
// baseline (speedup 1.0000x reference)
#include <cuda_runtime.h>
#include <cuda_fp16.h>
#include <cstdint>
#include <cstddef>

// ---------------- problem constants ----------------
#define TOK 16384
#define HD  2048
#define ID  4096
#define NG  4

// ---------------- device scratch ----------------
__device__ __half g_bufA[(size_t)TOK * HD];       // x in fp16
__device__ __half g_w2h [(size_t)HD * ID];        // w2 fp16 straight [HD][ID]
__device__ __half g_w1t [(size_t)HD * ID];        // w1^T fp16 [HD][ID]
__device__ __half g_l0g2[(size_t)NG * HD * ID];   // l0 g2 straight [G][HD][ID]
__device__ __half g_l0g1[(size_t)NG * HD * ID];   // l0 g1^T [G][HD][ID]
__device__ __half g_l1g2[(size_t)NG * HD * ID];
__device__ __half g_l1g1[(size_t)NG * HD * ID];
__device__ __half g_W12T[(size_t)HD * HD];        // (w2·w1)^T
__device__ __half g_G12a[(size_t)NG * HD * HD];   // g2·g1 layer 0
__device__ __half g_G12b[(size_t)NG * HD * HD];   // g2·g1 layer 1
__device__ __half g_Q   [(size_t)NG * HD * HD];   // (G12a·W12)^T
__device__ __half g_Mall[(size_t)NG * HD * HD];   // total weight [G][out][in]
__device__ float  g_bd  [HD];
__device__ float  g_bl0 [NG * HD];
__device__ float  g_bl1 [NG * HD];
__device__ float  g_bt  [NG * HD];
__device__ float  g_btot[NG * HD];
__device__ float  g_zbias[HD];                    // zero-initialized, never written

// ---------------- fused fp32 -> fp16 straight conversion ----------------
struct ConvJobs {
    const float4* src[4];
    __half2*      dst[4];
    unsigned long long off[5];
};

__global__ __launch_bounds__(256)
void f2h_fused_kernel(ConvJobs jobs) {
    unsigned long long i = (unsigned long long)blockIdx.x * blockDim.x + threadIdx.x;
    if (i >= jobs.off[4]) return;
#pragma unroll
    for (int j = 0; j < 4; ++j) {
        if (i < jobs.off[j + 1]) {
            unsigned long long r = i - jobs.off[j];
            float4 v = jobs.src[j][r];
            jobs.dst[j][2 * r]     = __floats2half2_rn(v.x, v.y);
            jobs.dst[j][2 * r + 1] = __floats2half2_rn(v.z, v.w);
            return;
        }
    }
}

// ---------------- fp32 -> fp16 transposed conversion ----------------
// src [B][R][Cc] fp32 -> dst [B][Cc][R] fp16
__global__ __launch_bounds__(256)
void f2h_T_kernel(const float* __restrict__ src, __half* __restrict__ dst, int R, int Cc) {
    __shared__ __half tile[32][34];
    const size_t base = (size_t)blockIdx.z * R * Cc;
    const int r0 = blockIdx.y * 32, c0 = blockIdx.x * 32;
    const int tx = threadIdx.x, ty = threadIdx.y;   // 32 x 8
#pragma unroll
    for (int i = 0; i < 32; i += 8)
        tile[ty + i][tx] = __float2half(src[base + (size_t)(r0 + ty + i) * Cc + c0 + tx]);
    __syncthreads();
#pragma unroll
    for (int i = 0; i < 32; i += 8)
        dst[base + (size_t)(c0 + ty + i) * R + r0 + tx] = tile[tx][ty + i];
}

// ---------------- bias GEMV: out[g][o] = sum_k W[g][o][k]*bin[g][k] + badd[g][o] ----------------
template <typename WT>
__global__ __launch_bounds__(256)
void bias_combine_kernel(const WT* __restrict__ W, const float* __restrict__ bin,
                         const float* __restrict__ badd, float* __restrict__ out,
                         int OUT, int KK, size_t wStride, size_t binStride) {
    const int g = blockIdx.y;
    const int wpb = blockDim.x / 32;
    const int o = blockIdx.x * wpb + (threadIdx.x >> 5);
    const int lane = threadIdx.x & 31;
    if (o >= OUT) return;
    const WT* wrow = W + g * wStride + (size_t)o * KK;
    const float* bi = bin + g * binStride;
    float s = 0.f;
    for (int k = lane; k < KK; k += 32) s += (float)wrow[k] * bi[k];
#pragma unroll
    for (int off = 16; off; off >>= 1) s += __shfl_xor_sync(0xFFFFFFFFu, s, off);
    if (lane == 0) out[(size_t)g * OUT + o] = s + badd[(size_t)g * OUT + o];
}

// ---------------- tile config (champion geometry) ----------------
constexpr int BM = 128, BN = 128, BK = 64;
constexpr int STAGES = 3;
constexpr int ASTG = BM * 128;
constexpr int BSTG = BN * 128;
constexpr int STG  = ASTG + BSTG;           // 32768 B per stage
constexpr int SMEM_BYTES = STAGES * STG;    // 98304 B -> 2 CTAs / SM

// ---------------- helpers ----------------
__device__ __forceinline__ uint32_t smem_u32(const void* p) {
    return (uint32_t)__cvta_generic_to_shared(p);
}
__device__ __forceinline__ uint32_t swz(uint32_t off) {
    return off ^ ((off >> 3) & 0x70);
}
__device__ __forceinline__ void cp16(uint32_t dst, const void* src) {
    asm volatile("cp.async.cg.shared.global [%0], [%1], 16;\n" :: "r"(dst), "l"(src));
}
__device__ __forceinline__ void cp_commit() { asm volatile("cp.async.commit_group;\n"); }
template <int N>
__device__ __forceinline__ void cp_wait() { asm volatile("cp.async.wait_group %0;\n" :: "n"(N)); }

__device__ __forceinline__ void ldsm_x4(uint32_t* r, uint32_t addr) {
    asm volatile("ldmatrix.sync.aligned.m8n8.x4.shared.b16 {%0,%1,%2,%3}, [%4];\n"
                 : "=r"(r[0]), "=r"(r[1]), "=r"(r[2]), "=r"(r[3]) : "r"(addr));
}
__device__ __forceinline__ void mma16816(float* c, const uint32_t* a, const uint32_t* b) {
    asm volatile("mma.sync.aligned.m16n8k16.row.col.f32.f16.f16.f32 "
                 "{%0,%1,%2,%3}, {%4,%5,%6,%7}, {%8,%9}, {%0,%1,%2,%3};\n"
                 : "+f"(c[0]), "+f"(c[1]), "+f"(c[2]), "+f"(c[3])
                 : "r"(a[0]), "r"(a[1]), "r"(a[2]), "r"(a[3]), "r"(b[0]), "r"(b[1]));
}

// ---------------- fp16 GEMM:  C[M,N] = A[M,K] * W[N,K]^T + bias ----------------
// Group selection: blockIdx.z if gridDim.z > 1, else bm / mRowsPerGroup.
// Per-group strides for A, W, bias, C allow shared or grouped operands.
template <typename OutT>
__global__ __launch_bounds__(256, 2)
void gemm_kernel(const __half* __restrict__ A, const __half* __restrict__ W,
                 const float* __restrict__ bias, OutT* __restrict__ C,
                 int N, int K, int mRowsPerGroup,
                 size_t aStride, size_t wStride, size_t bStride, size_t cStride) {
    extern __shared__ char smem_raw[];
    const uint32_t sbase = smem_u32(smem_raw);

    const int tid  = threadIdx.x;
    const int lane = tid & 31;
    const int warp = tid >> 5;
    const int wm   = warp >> 2;
    const int wn   = warp & 3;
    const int bm   = blockIdx.y * BM;
    const int bn   = blockIdx.x * BN;
    const int group = (gridDim.z > 1) ? blockIdx.z : (bm / mRowsPerGroup);

    const __half* gA = A + group * aStride + (size_t)bm * K;
    const __half* gW = W + group * wStride + (size_t)bn * K;
    const float*  gBias = bias + group * bStride + bn;
    OutT* gC = C + group * cStride;
    const int kTiles = K / BK;

    float acc[4][4][4];
#pragma unroll
    for (int a = 0; a < 4; a++)
#pragma unroll
        for (int b = 0; b < 4; b++)
#pragma unroll
            for (int c = 0; c < 4; c++) acc[a][b][c] = 0.f;

    auto load_stage = [&](int s, int kt) {
        const uint32_t dA = sbase + s * STG;
        const uint32_t dB = dA + ASTG;
        const __half* srcA = gA + kt * BK;
        const __half* srcB = gW + kt * BK;
#pragma unroll
        for (int i = 0; i < 4; i++) {
            int q = tid + i * 256;
            int r = q >> 3, c = q & 7;
            cp16(dA + swz((uint32_t)(r * 128 + c * 16)), srcA + (size_t)r * K + c * 8);
        }
#pragma unroll
        for (int i = 0; i < 4; i++) {
            int q = tid + i * 256;
            int r = q >> 3, c = q & 7;
            cp16(dB + swz((uint32_t)(r * 128 + c * 16)), srcB + (size_t)r * K + c * 8);
        }
    };

    load_stage(0, 0); cp_commit();
    if (kTiles > 1) load_stage(1, 1);
    cp_commit();

    for (int kt = 0; kt < kTiles; ++kt) {
        cp_wait<1>();
        __syncthreads();

        const int nk = kt + 2;
        if (nk < kTiles) load_stage(nk % STAGES, nk);
        cp_commit();

        const uint32_t cA = sbase + (kt % STAGES) * STG;
        const uint32_t cB = cA + ASTG;

#pragma unroll
        for (int ks = 0; ks < BK / 16; ++ks) {
            uint32_t aF[4][4], bF[4][2];
#pragma unroll
            for (int mi = 0; mi < 4; ++mi) {
                int r = wm * 64 + mi * 16 + (lane & 15);
                int c = ks * 16 + (lane >> 4) * 8;
                ldsm_x4(aF[mi], cA + swz((uint32_t)(r * 128 + c * 2)));
            }
#pragma unroll
            for (int np = 0; np < 2; ++np) {
                int r = wn * 32 + np * 16 + ((lane >> 4) & 1) * 8 + (lane & 7);
                int c = ks * 16 + ((lane >> 3) & 1) * 8;
                uint32_t t[4];
                ldsm_x4(t, cB + swz((uint32_t)(r * 128 + c * 2)));
                bF[2 * np][0] = t[0]; bF[2 * np][1] = t[1];
                bF[2 * np + 1][0] = t[2]; bF[2 * np + 1][1] = t[3];
            }
#pragma unroll
            for (int mi = 0; mi < 4; ++mi)
#pragma unroll
                for (int ni = 0; ni < 4; ++ni)
                    mma16816(acc[mi][ni], aF[mi], bF[ni]);
        }
    }

#pragma unroll
    for (int mi = 0; mi < 4; ++mi) {
#pragma unroll
        for (int ni = 0; ni < 4; ++ni) {
            int r0 = bm + wm * 64 + mi * 16 + (lane >> 2);
            int cb = wn * 32 + ni * 8 + (lane & 3) * 2;
            int c0 = bn + cb;
            float bv0 = gBias[cb], bv1 = gBias[cb + 1];
            float v0 = acc[mi][ni][0] + bv0;
            float v1 = acc[mi][ni][1] + bv1;
            float v2 = acc[mi][ni][2] + bv0;
            float v3 = acc[mi][ni][3] + bv1;
            if constexpr (sizeof(OutT) == 2) {
                *(__half2*)((__half*)gC + (size_t)r0 * N + c0)       = __floats2half2_rn(v0, v1);
                *(__half2*)((__half*)gC + (size_t)(r0 + 8) * N + c0) = __floats2half2_rn(v2, v3);
            } else {
                *(float2*)((float*)gC + (size_t)r0 * N + c0)       = make_float2(v0, v1);
                *(float2*)((float*)gC + (size_t)(r0 + 8) * N + c0) = make_float2(v2, v3);
            }
        }
    }
}

// ---------------- host launcher ----------------
static inline void* sym_addr(const void* symbol) {
    void* p = nullptr;
    cudaGetSymbolAddress(&p, symbol);
    return p;
}

extern "C" void kernel_launch(void* const* d_in, const int* in_sizes, int n_in,
                              void* d_out, int out_size) {
    const float* x    = (const float*)d_in[0];
    const float* w1   = (const float*)d_in[1];
    const float* b1   = (const float*)d_in[2];
    const float* w2   = (const float*)d_in[3];
    const float* b2   = (const float*)d_in[4];
    const float* g1w0 = (const float*)d_in[5];
    const float* g1b0 = (const float*)d_in[6];
    const float* g2w0 = (const float*)d_in[7];
    const float* g2b0 = (const float*)d_in[8];
    const float* g1w1 = (const float*)d_in[9];
    const float* g1b1 = (const float*)d_in[10];
    const float* g2w1 = (const float*)d_in[11];
    const float* g2b1 = (const float*)d_in[12];

    __half* bufA = (__half*)sym_addr(g_bufA);
    __half* w2h  = (__half*)sym_addr(g_w2h);
    __half* w1t  = (__half*)sym_addr(g_w1t);
    __half* l0g2 = (__half*)sym_addr(g_l0g2);
    __half* l0g1 = (__half*)sym_addr(g_l0g1);
    __half* l1g2 = (__half*)sym_addr(g_l1g2);
    __half* l1g1 = (__half*)sym_addr(g_l1g1);
    __half* W12T = (__half*)sym_addr(g_W12T);
    __half* G12a = (__half*)sym_addr(g_G12a);
    __half* G12b = (__half*)sym_addr(g_G12b);
    __half* Q    = (__half*)sym_addr(g_Q);
    __half* Mall = (__half*)sym_addr(g_Mall);
    float*  bd   = (float*)sym_addr(g_bd);
    float*  bl0  = (float*)sym_addr(g_bl0);
    float*  bl1  = (float*)sym_addr(g_bl1);
    float*  bt   = (float*)sym_addr(g_bt);
    float*  btot = (float*)sym_addr(g_btot);
    float*  zb   = (float*)sym_addr(g_zbias);

    cudaFuncSetAttribute(gemm_kernel<__half>, cudaFuncAttributeMaxDynamicSharedMemorySize, SMEM_BYTES);
    cudaFuncSetAttribute(gemm_kernel<float>,  cudaFuncAttributeMaxDynamicSharedMemorySize, SMEM_BYTES);

    const size_t HH = (size_t)HD * HD;
    const size_t HI = (size_t)HD * ID;

    // ---- straight conversions: x, w2, g2w0, g2w1 ----
    ConvJobs jobs;
    const float* srcs[4] = {x, w2, g2w0, g2w1};
    __half* dsts[4]      = {bufA, w2h, l0g2, l1g2};
    size_t counts[4] = {(size_t)TOK * HD, HI, NG * HI, NG * HI};
    unsigned long long acc = 0;
    for (int j = 0; j < 4; ++j) {
        jobs.src[j] = (const float4*)srcs[j];
        jobs.dst[j] = (__half2*)dsts[j];
        jobs.off[j] = acc;
        acc += counts[j] / 4;
    }
    jobs.off[4] = acc;
    f2h_fused_kernel<<<(unsigned)((acc + 255) / 256), 256>>>(jobs);

    // ---- transposed conversions ----
    {
        dim3 tb(32, 8);
        f2h_T_kernel<<<dim3(HD / 32, ID / 32, 1),  tb>>>(w1,   w1t,  ID, HD);
        f2h_T_kernel<<<dim3(HD / 32, ID / 32, NG), tb>>>(g1w0, l0g1, ID, HD);
        f2h_T_kernel<<<dim3(HD / 32, ID / 32, NG), tb>>>(g1w1, l1g1, ID, HD);
    }

    // ---- stage-level combined biases (fp32 weights) ----
    bias_combine_kernel<float><<<dim3(HD / 8, 1), 256>>>(w2,   b1,   b2,   bd,  HD, ID, 0, 0);
    bias_combine_kernel<float><<<dim3(HD / 8, NG), 256>>>(g2w0, g1b0, g2b0, bl0, HD, ID, HI, ID);
    bias_combine_kernel<float><<<dim3(HD / 8, NG), 256>>>(g2w1, g1b1, g2b1, bl1, HD, ID, HI, ID);

    // ---- weight combines ----
    // W12T[i][o] = sum_k w1t[i,k] * w2h[o,k]   ( = (w2·w1)^T )
    gemm_kernel<__half><<<dim3(HD / BN, HD / BM, 1), 256, SMEM_BYTES>>>(
        w1t, w2h, zb, W12T, HD, ID, HD, 0, 0, 0, 0);
    // G12a[g] = l0g2[g] · l0g1[g]^T-form  (grouped along M)
    gemm_kernel<__half><<<dim3(HD / BN, (NG * HD) / BM, 1), 256, SMEM_BYTES>>>(
        l0g2, l0g1, zb, G12a, HD, ID, HD, 0, HI, 0, 0);
    gemm_kernel<__half><<<dim3(HD / BN, (NG * HD) / BM, 1), 256, SMEM_BYTES>>>(
        l1g2, l1g1, zb, G12b, HD, ID, HD, 0, HI, 0, 0);
    // Q[g][i][o2] = sum_k W12T[i,k] * G12a[g][o2,k]   ( = (G12a·W12)^T )
    gemm_kernel<__half><<<dim3(HD / BN, HD / BM, NG), 256, SMEM_BYTES>>>(
        W12T, G12a, zb, Q, HD, HD, HD, 0, HH, 0, HH);
    // Mall[g][o3][i] = sum_k G12b[g][o3,k] * Q[g][i,k]
    gemm_kernel<__half><<<dim3(HD / BN, HD / BM, NG), 256, SMEM_BYTES>>>(
        G12b, Q, zb, Mall, HD, HD, HD, HH, HH, 0, HH);

    // ---- total bias: btot[g] = G12b[g]·(G12a[g]·bd + bl0[g]) + bl1[g] ----
    bias_combine_kernel<__half><<<dim3(HD / 8, NG), 256>>>(G12a, bd, bl0, bt,   HD, HD, HH, 0);
    bias_combine_kernel<__half><<<dim3(HD / 8, NG), 256>>>(G12b, bt, bl1, btot, HD, HD, HH, HD);

    // ---- single main pass: out = x · Mall[g]^T + btot[g] ----
    gemm_kernel<float><<<dim3(HD / BN, TOK / BM, 1), 256, SMEM_BYTES>>>(
        bufA, Mall, btot, (float*)d_out, HD, HD, TOK / NG, 0, HH, HD, 0);
}

// round 15
// speedup vs baseline: 1.5375x; 1.5375x over previous
#include <cuda_runtime.h>
#include <cuda_fp16.h>
#include <cstdint>
#include <cstddef>

// ---------------- problem constants ----------------
#define TOK 16384
#define HD  2048
#define ID  4096
#define NG  4

// ---------------- device scratch ----------------
__device__ __half g_bufA[(size_t)TOK * HD];       // x in fp16
__device__ __half g_w2h [(size_t)HD * ID];        // w2 fp16 straight [HD][ID]
__device__ __half g_w1t [(size_t)HD * ID];        // w1^T fp16 [HD][ID]
__device__ __half g_l0g2[(size_t)NG * HD * ID];   // l0 g2 straight [G][HD][ID]
__device__ __half g_l0g1[(size_t)NG * HD * ID];   // l0 g1^T [G][HD][ID]
__device__ __half g_l1g2[(size_t)NG * HD * ID];
__device__ __half g_l1g1[(size_t)NG * HD * ID];
__device__ __half g_W12T[(size_t)HD * HD];        // (w2·w1)^T
__device__ __half g_G12a[(size_t)NG * HD * HD];   // g2·g1 layer 0
__device__ __half g_G12b[(size_t)NG * HD * HD];   // g2·g1 layer 1
__device__ __half g_Q   [(size_t)NG * HD * HD];   // (G12a·W12)^T per group
__device__ __half g_Mall[(size_t)NG * HD * HD];   // total weight [G][out][in]
__device__ float  g_bd  [HD];
__device__ float  g_bl0 [NG * HD];
__device__ float  g_bl1 [NG * HD];
__device__ float  g_bt  [NG * HD];
__device__ float  g_btot[NG * HD];
__device__ float  g_zbias[NG * HD];               // zero-initialized, never written

// ---------------- fused fp32 -> fp16 straight conversion ----------------
struct ConvJobs {
    const float4* src[4];
    __half2*      dst[4];
    unsigned long long off[5];
};

__global__ __launch_bounds__(256)
void f2h_fused_kernel(ConvJobs jobs) {
    unsigned long long i = (unsigned long long)blockIdx.x * blockDim.x + threadIdx.x;
    if (i >= jobs.off[4]) return;
#pragma unroll
    for (int j = 0; j < 4; ++j) {
        if (i < jobs.off[j + 1]) {
            unsigned long long r = i - jobs.off[j];
            float4 v = jobs.src[j][r];
            jobs.dst[j][2 * r]     = __floats2half2_rn(v.x, v.y);
            jobs.dst[j][2 * r + 1] = __floats2half2_rn(v.z, v.w);
            return;
        }
    }
}

// ---------------- fp32 -> fp16 transposed conversion ----------------
// src [B][R][Cc] fp32 -> dst [B][Cc][R] fp16
__global__ __launch_bounds__(256)
void f2h_T_kernel(const float* __restrict__ src, __half* __restrict__ dst, int R, int Cc) {
    __shared__ __half tile[32][34];
    const size_t base = (size_t)blockIdx.z * R * Cc;
    const int r0 = blockIdx.y * 32, c0 = blockIdx.x * 32;
    const int tx = threadIdx.x, ty = threadIdx.y;   // 32 x 8
#pragma unroll
    for (int i = 0; i < 32; i += 8)
        tile[ty + i][tx] = __float2half(src[base + (size_t)(r0 + ty + i) * Cc + c0 + tx]);
    __syncthreads();
#pragma unroll
    for (int i = 0; i < 32; i += 8)
        dst[base + (size_t)(c0 + ty + i) * R + r0 + tx] = tile[tx][ty + i];
}

// ---------------- bias GEMV: out[g][o] = sum_k W[g][o][k]*bin[g][k] + badd[g][o] ----------------
template <typename WT>
__global__ __launch_bounds__(256)
void bias_combine_kernel(const WT* __restrict__ W, const float* __restrict__ bin,
                         const float* __restrict__ badd, float* __restrict__ out,
                         int OUT, int KK, size_t wStride, size_t binStride) {
    const int g = blockIdx.y;
    const int wpb = blockDim.x / 32;
    const int o = blockIdx.x * wpb + (threadIdx.x >> 5);
    const int lane = threadIdx.x & 31;
    if (o >= OUT) return;
    const WT* wrow = W + g * wStride + (size_t)o * KK;
    const float* bi = bin + g * binStride;
    float s = 0.f;
    for (int k = lane; k < KK; k += 32) s += (float)wrow[k] * bi[k];
#pragma unroll
    for (int off = 16; off; off >>= 1) s += __shfl_xor_sync(0xFFFFFFFFu, s, off);
    if (lane == 0) out[(size_t)g * OUT + o] = s + badd[(size_t)g * OUT + o];
}

// ---------------- tile config (champion geometry) ----------------
constexpr int BM = 128, BN = 128, BK = 64;
constexpr int STAGES = 3;
constexpr int ASTG = BM * 128;
constexpr int BSTG = BN * 128;
constexpr int STG  = ASTG + BSTG;           // 32768 B per stage
constexpr int SMEM_BYTES = STAGES * STG;    // 98304 B -> 2 CTAs / SM

// ---------------- helpers ----------------
__device__ __forceinline__ uint32_t smem_u32(const void* p) {
    return (uint32_t)__cvta_generic_to_shared(p);
}
__device__ __forceinline__ uint32_t swz(uint32_t off) {
    return off ^ ((off >> 3) & 0x70);
}
__device__ __forceinline__ void cp16(uint32_t dst, const void* src) {
    asm volatile("cp.async.cg.shared.global [%0], [%1], 16;\n" :: "r"(dst), "l"(src));
}
__device__ __forceinline__ void cp_commit() { asm volatile("cp.async.commit_group;\n"); }
template <int N>
__device__ __forceinline__ void cp_wait() { asm volatile("cp.async.wait_group %0;\n" :: "n"(N)); }

__device__ __forceinline__ void ldsm_x4(uint32_t* r, uint32_t addr) {
    asm volatile("ldmatrix.sync.aligned.m8n8.x4.shared.b16 {%0,%1,%2,%3}, [%4];\n"
                 : "=r"(r[0]), "=r"(r[1]), "=r"(r[2]), "=r"(r[3]) : "r"(addr));
}
__device__ __forceinline__ void mma16816(float* c, const uint32_t* a, const uint32_t* b) {
    asm volatile("mma.sync.aligned.m16n8k16.row.col.f32.f16.f16.f32 "
                 "{%0,%1,%2,%3}, {%4,%5,%6,%7}, {%8,%9}, {%0,%1,%2,%3};\n"
                 : "+f"(c[0]), "+f"(c[1]), "+f"(c[2]), "+f"(c[3])
                 : "r"(a[0]), "r"(a[1]), "r"(a[2]), "r"(a[3]), "r"(b[0]), "r"(b[1]));
}

// ---------------- champion fp16 GEMM (R13 signature, UNMODIFIED) ----------------
//  C[M,N] = A[M,K] * W[N,K]^T + bias ; grouped along M: group = bm / mRowsPerGroup.
template <typename OutT>
__global__ __launch_bounds__(256, 2)
void gemm_kernel(const __half* __restrict__ A, const __half* __restrict__ W,
                 const float* __restrict__ bias, OutT* __restrict__ C,
                 int N, int K, int mRowsPerGroup) {
    extern __shared__ char smem_raw[];
    const uint32_t sbase = smem_u32(smem_raw);

    const int tid  = threadIdx.x;
    const int lane = tid & 31;
    const int warp = tid >> 5;
    const int wm   = warp >> 2;
    const int wn   = warp & 3;
    const int bm   = blockIdx.y * BM;
    const int bn   = blockIdx.x * BN;
    const int group = bm / mRowsPerGroup;

    const __half* gA = A + (size_t)bm * K;
    const __half* gW = W + (size_t)group * N * K + (size_t)bn * K;
    const float*  gBias = bias + (size_t)group * N + bn;
    const int kTiles = K / BK;

    float acc[4][4][4];
#pragma unroll
    for (int a = 0; a < 4; a++)
#pragma unroll
        for (int b = 0; b < 4; b++)
#pragma unroll
            for (int c = 0; c < 4; c++) acc[a][b][c] = 0.f;

    auto load_stage = [&](int s, int kt) {
        const uint32_t dA = sbase + s * STG;
        const uint32_t dB = dA + ASTG;
        const __half* srcA = gA + kt * BK;
        const __half* srcB = gW + kt * BK;
#pragma unroll
        for (int i = 0; i < 4; i++) {
            int q = tid + i * 256;
            int r = q >> 3, c = q & 7;
            cp16(dA + swz((uint32_t)(r * 128 + c * 16)), srcA + (size_t)r * K + c * 8);
        }
#pragma unroll
        for (int i = 0; i < 4; i++) {
            int q = tid + i * 256;
            int r = q >> 3, c = q & 7;
            cp16(dB + swz((uint32_t)(r * 128 + c * 16)), srcB + (size_t)r * K + c * 8);
        }
    };

    load_stage(0, 0); cp_commit();
    if (kTiles > 1) load_stage(1, 1);
    cp_commit();

    for (int kt = 0; kt < kTiles; ++kt) {
        cp_wait<1>();
        __syncthreads();

        const int nk = kt + 2;
        if (nk < kTiles) load_stage(nk % STAGES, nk);
        cp_commit();

        const uint32_t cA = sbase + (kt % STAGES) * STG;
        const uint32_t cB = cA + ASTG;

#pragma unroll
        for (int ks = 0; ks < BK / 16; ++ks) {
            uint32_t aF[4][4], bF[4][2];
#pragma unroll
            for (int mi = 0; mi < 4; ++mi) {
                int r = wm * 64 + mi * 16 + (lane & 15);
                int c = ks * 16 + (lane >> 4) * 8;
                ldsm_x4(aF[mi], cA + swz((uint32_t)(r * 128 + c * 2)));
            }
#pragma unroll
            for (int np = 0; np < 2; ++np) {
                int r = wn * 32 + np * 16 + ((lane >> 4) & 1) * 8 + (lane & 7);
                int c = ks * 16 + ((lane >> 3) & 1) * 8;
                uint32_t t[4];
                ldsm_x4(t, cB + swz((uint32_t)(r * 128 + c * 2)));
                bF[2 * np][0] = t[0]; bF[2 * np][1] = t[1];
                bF[2 * np + 1][0] = t[2]; bF[2 * np + 1][1] = t[3];
            }
#pragma unroll
            for (int mi = 0; mi < 4; ++mi)
#pragma unroll
                for (int ni = 0; ni < 4; ++ni)
                    mma16816(acc[mi][ni], aF[mi], bF[ni]);
        }
    }

#pragma unroll
    for (int mi = 0; mi < 4; ++mi) {
#pragma unroll
        for (int ni = 0; ni < 4; ++ni) {
            int r0 = bm + wm * 64 + mi * 16 + (lane >> 2);
            int cb = wn * 32 + ni * 8 + (lane & 3) * 2;
            int c0 = bn + cb;
            float bv0 = gBias[cb], bv1 = gBias[cb + 1];
            float v0 = acc[mi][ni][0] + bv0;
            float v1 = acc[mi][ni][1] + bv1;
            float v2 = acc[mi][ni][2] + bv0;
            float v3 = acc[mi][ni][3] + bv1;
            if constexpr (sizeof(OutT) == 2) {
                *(__half2*)((__half*)C + (size_t)r0 * N + c0)       = __floats2half2_rn(v0, v1);
                *(__half2*)((__half*)C + (size_t)(r0 + 8) * N + c0) = __floats2half2_rn(v2, v3);
            } else {
                *(float2*)((float*)C + (size_t)r0 * N + c0)       = make_float2(v0, v1);
                *(float2*)((float*)C + (size_t)(r0 + 8) * N + c0) = make_float2(v2, v3);
            }
        }
    }
}

// ---------------- z-grouped HDxHD GEMM (isolated clone; no bias, fp16 out) ----------------
// C[g][M,N] = A([g])[M,K] * W[g][N,K]^T   with N=K=HD, group = blockIdx.z
template <bool ASHARED>
__global__ __launch_bounds__(256, 2)
void gemm_hh_kernel(const __half* __restrict__ A, const __half* __restrict__ W,
                    __half* __restrict__ C) {
    extern __shared__ char smem_raw[];
    const uint32_t sbase = smem_u32(smem_raw);
    constexpr int N = HD, K = HD;
    constexpr size_t HH = (size_t)HD * HD;

    const int tid  = threadIdx.x;
    const int lane = tid & 31;
    const int warp = tid >> 5;
    const int wm   = warp >> 2;
    const int wn   = warp & 3;
    const int bm   = blockIdx.y * BM;
    const int bn   = blockIdx.x * BN;
    const int group = blockIdx.z;

    const __half* gA = A + (ASHARED ? (size_t)0 : group * HH) + (size_t)bm * K;
    const __half* gW = W + group * HH + (size_t)bn * K;
    __half* gC = C + group * HH;
    constexpr int kTiles = K / BK;

    float acc[4][4][4];
#pragma unroll
    for (int a = 0; a < 4; a++)
#pragma unroll
        for (int b = 0; b < 4; b++)
#pragma unroll
            for (int c = 0; c < 4; c++) acc[a][b][c] = 0.f;

    auto load_stage = [&](int s, int kt) {
        const uint32_t dA = sbase + s * STG;
        const uint32_t dB = dA + ASTG;
        const __half* srcA = gA + kt * BK;
        const __half* srcB = gW + kt * BK;
#pragma unroll
        for (int i = 0; i < 4; i++) {
            int q = tid + i * 256;
            int r = q >> 3, c = q & 7;
            cp16(dA + swz((uint32_t)(r * 128 + c * 16)), srcA + (size_t)r * K + c * 8);
        }
#pragma unroll
        for (int i = 0; i < 4; i++) {
            int q = tid + i * 256;
            int r = q >> 3, c = q & 7;
            cp16(dB + swz((uint32_t)(r * 128 + c * 16)), srcB + (size_t)r * K + c * 8);
        }
    };

    load_stage(0, 0); cp_commit();
    load_stage(1, 1); cp_commit();

    for (int kt = 0; kt < kTiles; ++kt) {
        cp_wait<1>();
        __syncthreads();

        const int nk = kt + 2;
        if (nk < kTiles) load_stage(nk % STAGES, nk);
        cp_commit();

        const uint32_t cA = sbase + (kt % STAGES) * STG;
        const uint32_t cB = cA + ASTG;

#pragma unroll
        for (int ks = 0; ks < BK / 16; ++ks) {
            uint32_t aF[4][4], bF[4][2];
#pragma unroll
            for (int mi = 0; mi < 4; ++mi) {
                int r = wm * 64 + mi * 16 + (lane & 15);
                int c = ks * 16 + (lane >> 4) * 8;
                ldsm_x4(aF[mi], cA + swz((uint32_t)(r * 128 + c * 2)));
            }
#pragma unroll
            for (int np = 0; np < 2; ++np) {
                int r = wn * 32 + np * 16 + ((lane >> 4) & 1) * 8 + (lane & 7);
                int c = ks * 16 + ((lane >> 3) & 1) * 8;
                uint32_t t[4];
                ldsm_x4(t, cB + swz((uint32_t)(r * 128 + c * 2)));
                bF[2 * np][0] = t[0]; bF[2 * np][1] = t[1];
                bF[2 * np + 1][0] = t[2]; bF[2 * np + 1][1] = t[3];
            }
#pragma unroll
            for (int mi = 0; mi < 4; ++mi)
#pragma unroll
                for (int ni = 0; ni < 4; ++ni)
                    mma16816(acc[mi][ni], aF[mi], bF[ni]);
        }
    }

#pragma unroll
    for (int mi = 0; mi < 4; ++mi) {
#pragma unroll
        for (int ni = 0; ni < 4; ++ni) {
            int r0 = bm + wm * 64 + mi * 16 + (lane >> 2);
            int c0 = bn + wn * 32 + ni * 8 + (lane & 3) * 2;
            *(__half2*)(gC + (size_t)r0 * N + c0)       = __floats2half2_rn(acc[mi][ni][0], acc[mi][ni][1]);
            *(__half2*)(gC + (size_t)(r0 + 8) * N + c0) = __floats2half2_rn(acc[mi][ni][2], acc[mi][ni][3]);
        }
    }
}

// ---------------- host launcher ----------------
static inline void* sym_addr(const void* symbol) {
    void* p = nullptr;
    cudaGetSymbolAddress(&p, symbol);
    return p;
}

extern "C" void kernel_launch(void* const* d_in, const int* in_sizes, int n_in,
                              void* d_out, int out_size) {
    const float* x    = (const float*)d_in[0];
    const float* w1   = (const float*)d_in[1];
    const float* b1   = (const float*)d_in[2];
    const float* w2   = (const float*)d_in[3];
    const float* b2   = (const float*)d_in[4];
    const float* g1w0 = (const float*)d_in[5];
    const float* g1b0 = (const float*)d_in[6];
    const float* g2w0 = (const float*)d_in[7];
    const float* g2b0 = (const float*)d_in[8];
    const float* g1w1 = (const float*)d_in[9];
    const float* g1b1 = (const float*)d_in[10];
    const float* g2w1 = (const float*)d_in[11];
    const float* g2b1 = (const float*)d_in[12];

    __half* bufA = (__half*)sym_addr(g_bufA);
    __half* w2h  = (__half*)sym_addr(g_w2h);
    __half* w1t  = (__half*)sym_addr(g_w1t);
    __half* l0g2 = (__half*)sym_addr(g_l0g2);
    __half* l0g1 = (__half*)sym_addr(g_l0g1);
    __half* l1g2 = (__half*)sym_addr(g_l1g2);
    __half* l1g1 = (__half*)sym_addr(g_l1g1);
    __half* W12T = (__half*)sym_addr(g_W12T);
    __half* G12a = (__half*)sym_addr(g_G12a);
    __half* G12b = (__half*)sym_addr(g_G12b);
    __half* Q    = (__half*)sym_addr(g_Q);
    __half* Mall = (__half*)sym_addr(g_Mall);
    float*  bd   = (float*)sym_addr(g_bd);
    float*  bl0  = (float*)sym_addr(g_bl0);
    float*  bl1  = (float*)sym_addr(g_bl1);
    float*  bt   = (float*)sym_addr(g_bt);
    float*  btot = (float*)sym_addr(g_btot);
    float*  zb   = (float*)sym_addr(g_zbias);

    cudaFuncSetAttribute(gemm_kernel<__half>, cudaFuncAttributeMaxDynamicSharedMemorySize, SMEM_BYTES);
    cudaFuncSetAttribute(gemm_kernel<float>,  cudaFuncAttributeMaxDynamicSharedMemorySize, SMEM_BYTES);
    cudaFuncSetAttribute(gemm_hh_kernel<true>,  cudaFuncAttributeMaxDynamicSharedMemorySize, SMEM_BYTES);
    cudaFuncSetAttribute(gemm_hh_kernel<false>, cudaFuncAttributeMaxDynamicSharedMemorySize, SMEM_BYTES);

    const size_t HI = (size_t)HD * ID;
    const size_t HH = (size_t)HD * HD;

    // ---- straight conversions: x, w2, g2w0, g2w1 ----
    ConvJobs jobs;
    const float* srcs[4] = {x, w2, g2w0, g2w1};
    __half* dsts[4]      = {bufA, w2h, l0g2, l1g2};
    size_t counts[4] = {(size_t)TOK * HD, HI, NG * HI, NG * HI};
    unsigned long long acc = 0;
    for (int j = 0; j < 4; ++j) {
        jobs.src[j] = (const float4*)srcs[j];
        jobs.dst[j] = (__half2*)dsts[j];
        jobs.off[j] = acc;
        acc += counts[j] / 4;
    }
    jobs.off[4] = acc;
    f2h_fused_kernel<<<(unsigned)((acc + 255) / 256), 256>>>(jobs);

    // ---- transposed conversions ----
    {
        dim3 tb(32, 8);
        f2h_T_kernel<<<dim3(HD / 32, ID / 32, 1),  tb>>>(w1,   w1t,  ID, HD);
        f2h_T_kernel<<<dim3(HD / 32, ID / 32, NG), tb>>>(g1w0, l0g1, ID, HD);
        f2h_T_kernel<<<dim3(HD / 32, ID / 32, NG), tb>>>(g1w1, l1g1, ID, HD);
    }

    // ---- stage-level combined biases (fp32 weights) ----
    bias_combine_kernel<float><<<dim3(HD / 8, 1), 256>>>(w2,   b1,   b2,   bd,  HD, ID, 0, 0);
    bias_combine_kernel<float><<<dim3(HD / 8, NG), 256>>>(g2w0, g1b0, g2b0, bl0, HD, ID, HI, ID);
    bias_combine_kernel<float><<<dim3(HD / 8, NG), 256>>>(g2w1, g1b1, g2b1, bl1, HD, ID, HI, ID);

    // ---- stage-pair weight combines (champion kernel, M-grouped) ----
    // W12T[i][o] = sum_k w1t[i,k] * w2h[o,k] = (w2·w1)^T
    gemm_kernel<__half><<<dim3(HD / BN, HD / BM), 256, SMEM_BYTES>>>(
        w1t, w2h, zb, W12T, HD, ID, HD);
    gemm_kernel<__half><<<dim3(HD / BN, (NG * HD) / BM), 256, SMEM_BYTES>>>(
        l0g2, l0g1, zb, G12a, HD, ID, HD);
    gemm_kernel<__half><<<dim3(HD / BN, (NG * HD) / BM), 256, SMEM_BYTES>>>(
        l1g2, l1g1, zb, G12b, HD, ID, HD);

    // ---- full collapse (isolated z-grouped kernel) ----
    // Q[g][i][o2] = sum_k W12T[i,k] * G12a[g][o2,k]  ( = (G12a·W12)^T )
    gemm_hh_kernel<true><<<dim3(HD / BN, HD / BM, NG), 256, SMEM_BYTES>>>(W12T, G12a, Q);
    // Mall[g][o3][i] = sum_k G12b[g][o3,k] * Q[g][i,k]  ( = G12b·G12a·W12 )
    gemm_hh_kernel<false><<<dim3(HD / BN, HD / BM, NG), 256, SMEM_BYTES>>>(G12b, Q, Mall);

    // ---- total bias: btot[g] = G12b[g]·(G12a[g]·bd + bl0[g]) + bl1[g] ----
    bias_combine_kernel<__half><<<dim3(HD / 8, NG), 256>>>(G12a, bd, bl0, bt,   HD, HD, HH, 0);
    bias_combine_kernel<__half><<<dim3(HD / 8, NG), 256>>>(G12b, bt, bl1, btot, HD, HD, HH, HD);

    // ---- single main pass: out = x · Mall[g]^T + btot[g] ----
    gemm_kernel<float><<<dim3(HD / BN, TOK / BM), 256, SMEM_BYTES>>>(
        bufA, Mall, btot, (float*)d_out, HD, HD, TOK / NG);
}